// round 14
// baseline (speedup 1.0000x reference)
#include <cuda_runtime.h>
#include <cuda_bf16.h>
#include <cstdint>

#define NN   65536          // total nodes (G*N)
#define FIN  64
#define DD   128
#define RR   4
#define EE   1572864
#define GG   512
#define SEGS (NN*RR)        // 262144 (node,relation) segments
#define KCAT (RR*DD)        // 512
#define KTOT 640            // 128 (root) + 512 (rel)

// ---- scratch (static device globals; no runtime allocation) ----
// h stored pre-split as bf16 hi/lo (ping-pong buffers 0/1)
__device__ __align__(16) __nv_bfloat16 g_hH[2][(size_t)NN*DD];   // 2 x 16 MB
__device__ __align__(16) __nv_bfloat16 g_hL[2][(size_t)NN*DD];
__device__ __align__(16) __nv_bfloat16 g_mnH[(size_t)SEGS*DD];   // 67 MB
__device__ __align__(16) __nv_bfloat16 g_mnL[(size_t)SEGS*DD];
__device__ __align__(16) int   g_cnt[SEGS];
__device__ __align__(16) int   g_off[SEGS];
__device__ int   g_cur[SEGS];
__device__ int   g_bsum[256];
__device__ int   g_csr[EE];
// weights split to bf16 hi/lo, transposed to [layer][n=128][k=640]
__device__ __align__(16) __nv_bfloat16 g_Bhi[2*128*KTOT];
__device__ __align__(16) __nv_bfloat16 g_Blo[2*128*KTOT];

// ---------------- helpers ----------------
__device__ __forceinline__ uint32_t smem_u32(const void* p) {
    uint32_t a;
    asm("{ .reg .u64 t; cvta.to.shared.u64 t, %1; cvt.u32.u64 %0, t; }" : "=r"(a) : "l"(p));
    return a;
}
#define SWZ(o) ((o) ^ (((o) >> 3) & 0x70))

__device__ __forceinline__ void bsplit2(float x, float y, uint32_t& hi, uint32_t& lo) {
    __nv_bfloat162 h = __floats2bfloat162_rn(x, y);
    float rx = x - __bfloat162float(__low2bfloat16(h));
    float ry = y - __bfloat162float(__high2bfloat16(h));
    __nv_bfloat162 l = __floats2bfloat162_rn(rx, ry);
    hi = *(uint32_t*)&h; lo = *(uint32_t*)&l;
}
__device__ __forceinline__ float2 bjoin2(uint32_t h, uint32_t l) {
    float2 fh = __bfloat1622float2(*(__nv_bfloat162*)&h);
    float2 fl = __bfloat1622float2(*(__nv_bfloat162*)&l);
    return make_float2(fh.x + fl.x, fh.y + fl.y);
}

__device__ __forceinline__ void ldm_x4(uint32_t* r, uint32_t addr) {
    asm volatile("ldmatrix.sync.aligned.m8n8.x4.shared.b16 {%0,%1,%2,%3}, [%4];"
        : "=r"(r[0]), "=r"(r[1]), "=r"(r[2]), "=r"(r[3]) : "r"(addr));
}
__device__ __forceinline__ void ldm_x2(uint32_t* r, uint32_t addr) {
    asm volatile("ldmatrix.sync.aligned.m8n8.x2.shared.b16 {%0,%1}, [%2];"
        : "=r"(r[0]), "=r"(r[1]) : "r"(addr));
}
__device__ __forceinline__ void mma16816(float* c, const uint32_t* a, const uint32_t* b) {
    asm volatile("mma.sync.aligned.m16n8k16.row.col.f32.bf16.bf16.f32 "
        "{%0,%1,%2,%3}, {%4,%5,%6,%7}, {%8,%9}, {%0,%1,%2,%3};"
        : "+f"(c[0]), "+f"(c[1]), "+f"(c[2]), "+f"(c[3])
        : "r"(a[0]), "r"(a[1]), "r"(a[2]), "r"(a[3]), "r"(b[0]), "r"(b[1]));
}

// ---------------- CSR build ----------------
__global__ void k_zero_cnt() {
    int i = blockIdx.x*blockDim.x + threadIdx.x;
    if (i < SEGS) g_cnt[i] = 0;
}
__global__ void k_count(const int* __restrict__ ei, const int* __restrict__ ea) {
    int e = blockIdx.x*blockDim.x + threadIdx.x;
    if (e < EE) atomicAdd(&g_cnt[ei[EE + e]*RR + ea[e]], 1);
}
__global__ void k_scan1() {
    __shared__ int s[256];
    int tid = threadIdx.x;
    int base = blockIdx.x*1024 + tid*4;
    int4 c = *(const int4*)&g_cnt[base];
    int sum = c.x + c.y + c.z + c.w;
    s[tid] = sum;
    __syncthreads();
    #pragma unroll
    for (int off = 1; off < 256; off <<= 1) {
        int v = (tid >= off) ? s[tid - off] : 0;
        __syncthreads(); s[tid] += v; __syncthreads();
    }
    int excl = s[tid] - sum;
    int4 o; o.x = excl; o.y = o.x + c.x; o.z = o.y + c.y; o.w = o.z + c.z;
    *(int4*)&g_off[base] = o;
    if (tid == 255) g_bsum[blockIdx.x] = s[255];
}
__global__ void k_scan2() {
    __shared__ int s[256];
    int tid = threadIdx.x;
    int v0 = g_bsum[tid];
    s[tid] = v0;
    __syncthreads();
    #pragma unroll
    for (int off = 1; off < 256; off <<= 1) {
        int v = (tid >= off) ? s[tid - off] : 0;
        __syncthreads(); s[tid] += v; __syncthreads();
    }
    g_bsum[tid] = s[tid] - v0;
}
__global__ void k_scan3() {
    int i = blockIdx.x*blockDim.x + threadIdx.x;
    int o = g_off[i] + g_bsum[i >> 10];
    g_off[i] = o; g_cur[i] = o;
}
__global__ void k_fill(const int* __restrict__ ei, const int* __restrict__ ea) {
    int e = blockIdx.x*blockDim.x + threadIdx.x;
    if (e >= EE) return;
    int seg = ei[EE + e]*RR + ea[e];
    int pos = atomicAdd(&g_cur[seg], 1);
    g_csr[pos] = ei[e];
}

// ---------------- weight split: Wcat[k][n] -> bf16 hi/lo at [l][n][k] -------
__global__ void k_wsplit(const float* __restrict__ W_root, const float* __restrict__ W_rel) {
    int idx = blockIdx.x*blockDim.x + threadIdx.x;     // 2*640*128
    int l = idx / (KTOT*DD);
    int rem = idx - l*(KTOT*DD);
    int k = rem >> 7, n = rem & 127;
    float w = (k < DD) ? W_root[(size_t)l*DD*DD + k*DD + n]
                       : W_rel[(size_t)l*KCAT*DD + (k - DD)*DD + n];
    __nv_bfloat16 hi = __float2bfloat16_rn(w);
    __nv_bfloat16 lo = __float2bfloat16_rn(w - __bfloat162float(hi));
    size_t d = ((size_t)l*DD + n)*KTOT + k;
    g_Bhi[d] = hi; g_Blo[d] = lo;
}

// ---------------- embed: h = x @ W_emb + b_emb, write bf16 hi/lo ------------
__global__ __launch_bounds__(256) void k_embed(
    const float* __restrict__ x, const float* __restrict__ W,
    const float* __restrict__ b,
    __nv_bfloat16* __restrict__ outH, __nv_bfloat16* __restrict__ outL)
{
    __shared__ float xs[64][64];
    __shared__ float ws[64][128];
    int tid = threadIdx.x;
    int row0 = blockIdx.x * 64;
    #pragma unroll
    for (int i = 0; i < 4; i++) {
        int id = i*256 + tid;
        int r = id >> 4, c4 = (id & 15) * 4;
        *(float4*)&xs[r][c4] = *(const float4*)(x + (size_t)(row0 + r)*FIN + c4);
    }
    #pragma unroll
    for (int i = 0; i < 8; i++) {
        int id = i*256 + tid;
        int r = id >> 5, c4 = (id & 31) * 4;
        *(float4*)&ws[r][c4] = *(const float4*)(W + r*DD + c4);
    }
    __syncthreads();
    int ty = tid >> 5, tx = tid & 31;
    float acc[8][4] = {};
    #pragma unroll
    for (int k = 0; k < 64; k++) {
        float4 wv = *(const float4*)&ws[k][tx*4];
        #pragma unroll
        for (int i = 0; i < 8; i++) {
            float xv = xs[ty*8 + i][k];
            acc[i][0] += xv*wv.x; acc[i][1] += xv*wv.y;
            acc[i][2] += xv*wv.z; acc[i][3] += xv*wv.w;
        }
    }
    float4 bv = *(const float4*)(b + tx*4);
    #pragma unroll
    for (int i = 0; i < 8; i++) {
        float vx = acc[i][0] + bv.x, vy = acc[i][1] + bv.y;
        float vz = acc[i][2] + bv.z, vw = acc[i][3] + bv.w;
        uint2 hp, lp;
        bsplit2(vx, vy, hp.x, lp.x);
        bsplit2(vz, vw, hp.y, lp.y);
        size_t o = (size_t)(row0 + ty*8 + i)*DD + tx*4;   // bf16 elems
        *(uint2*)(outH + o) = hp;
        *(uint2*)(outL + o) = lp;
    }
}

// ---------------- gather-mean, per-graph smem version ------------------------
// One CTA per graph: reconstruct the graph's 128x128 h tile (hi+lo) in smem,
// compute all 512 (node,relation) segment means, write them pre-split bf16.
__global__ __launch_bounds__(512) void k_gather_g(
    const __nv_bfloat16* __restrict__ hH, const __nv_bfloat16* __restrict__ hL)
{
    extern __shared__ float hs[];                 // 128 x 128 fp32 = 64 KB
    int g = blockIdx.x;
    int tid = threadIdx.x;

    const uint2* srcH = (const uint2*)(hH + (size_t)g*128*DD);  // 4 bf16 per uint2
    const uint2* srcL = (const uint2*)(hL + (size_t)g*128*DD);
    #pragma unroll
    for (int i = 0; i < 8; i++) {                 // 4096 float4-slots / 512 thr
        int idx = i*512 + tid;
        uint2 hh = srcH[idx], ll = srcL[idx];
        float2 f0 = bjoin2(hh.x, ll.x);
        float2 f1 = bjoin2(hh.y, ll.y);
        ((float4*)hs)[idx] = make_float4(f0.x, f0.y, f1.x, f1.y);
    }
    __syncthreads();

    int wid = tid >> 5, lane = tid & 31;
    #pragma unroll 1
    for (int s = wid; s < 512; s += 16) {
        int seg = g*512 + s;
        int beg = g_off[seg], n = g_cnt[seg];
        float4 acc = make_float4(0.f, 0.f, 0.f, 0.f);
        const float* hb = hs + lane*4;
        int i = 0;
        for (; i + 2 <= n; i += 2) {
            int s0 = g_csr[beg + i] & 127, s1 = g_csr[beg + i + 1] & 127;
            float4 v0 = *(const float4*)(hb + s0*DD);
            float4 v1 = *(const float4*)(hb + s1*DD);
            acc.x += v0.x + v1.x; acc.y += v0.y + v1.y;
            acc.z += v0.z + v1.z; acc.w += v0.w + v1.w;
        }
        if (i < n) {
            float4 v0 = *(const float4*)(hb + (g_csr[beg + i] & 127)*DD);
            acc.x += v0.x; acc.y += v0.y; acc.z += v0.z; acc.w += v0.w;
        }
        float inv = 1.0f / (float)(n > 0 ? n : 1);
        uint2 hp, lp;
        bsplit2(acc.x*inv, acc.y*inv, hp.x, lp.x);
        bsplit2(acc.z*inv, acc.w*inv, hp.y, lp.y);
        size_t o = (size_t)seg*DD + lane*4;
        *(uint2*)(g_mnH + o) = hp;
        *(uint2*)(g_mnL + o) = lp;
    }
}

// ---------------- tensor-core GEMM via mma.sync ------------------------------
// C = relu([h | means] @ [W_root; W_rel] + bias), bf16x3 HMMA.
// A operands arrive PRE-SPLIT bf16 hi/lo -> A stage is a pure uint4 copy.
// BM=128, BN=128, BK=64, 8 warps 2(m)x4(n), warp tile 64x32.
// smem: Ahi@0 Alo@16K Bhi@32K Blo@48K, SW128-swizzled 128B rows.
// POOL=true: CTA == one graph; max-reduce relu outputs into out[g].
#define GEMM_SMEM 65536

template<bool POOL>
__global__ __launch_bounds__(256, 2) void k_gemm_mma(
    const __nv_bfloat16* __restrict__ AH, const __nv_bfloat16* __restrict__ AL,
    const __nv_bfloat16* __restrict__ Bhi,
    const __nv_bfloat16* __restrict__ Blo,
    const float* __restrict__ bias,
    __nv_bfloat16* __restrict__ CH, __nv_bfloat16* __restrict__ CL,
    float* __restrict__ Cpool)
{
    extern __shared__ char smem[];
    uint32_t sb = smem_u32(smem);
    const uint32_t sbAhi = sb, sbAlo = sb + 16384, sbBhi = sb + 32768, sbBlo = sb + 49152;
    int tid = threadIdx.x, wid = tid >> 5, lane = tid & 31;
    int wm = wid >> 2, wn = wid & 3;            // 2 x 4 warp grid
    int row0 = blockIdx.x * 128;

    float acc[4][4][4];
    #pragma unroll
    for (int i = 0; i < 4; i++)
        #pragma unroll
        for (int j = 0; j < 4; j++)
            #pragma unroll
            for (int q = 0; q < 4; q++) acc[i][j][q] = 0.f;

    for (int kc = 0; kc < 10; kc++) {
        // A source: root chunks read h, rel chunks read mn (seg = node*RR+rel)
        const __nv_bfloat16 *srcH, *srcL; int rs; int off;
        if (kc < 2) { srcH = AH;    srcL = AL;    rs = DD;   off = kc*64; }
        else {
            int rel = (kc - 2) >> 1, half = (kc - 2) & 1;
            srcH = g_mnH; srcL = g_mnL; rs = KCAT; off = rel*DD + half*64;
        }

        __syncthreads();   // previous iteration's consumers done with smem
        // A: pure copy, 128 rows x 64 bf16 per buffer (uint4 = 8 bf16)
        #pragma unroll
        for (int i = 0; i < 4; i++) {
            int id = i*256 + tid;                 // 0..1023
            int r = id >> 3, c8 = (id & 7) * 8;
            size_t gs = (size_t)(row0 + r)*rs + off + c8;
            uint32_t so = SWZ((uint32_t)(r*128 + c8*2));
            *(uint4*)(smem + so)         = *(const uint4*)(srcH + gs);
            *(uint4*)(smem + 16384 + so) = *(const uint4*)(srcL + gs);
        }
        // B: 128 n-rows x 64 k-cols bf16 from pre-split [n][k] arrays
        int k0 = kc * 64;
        #pragma unroll
        for (int i = 0; i < 4; i++) {
            int id = i*256 + tid;                 // 0..1023
            int n = id >> 3, c8 = (id & 7) * 8;
            size_t gs = (size_t)n*KTOT + k0 + c8;
            uint32_t so = SWZ((uint32_t)(n*128 + c8*2));
            *(uint4*)(smem + 32768 + so) = *(const uint4*)(Bhi + gs);
            *(uint4*)(smem + 49152 + so) = *(const uint4*)(Blo + gs);
        }
        __syncthreads();

        #pragma unroll
        for (int ks = 0; ks < 4; ks++) {
            int kb = ks * 16;
            uint32_t bhi[4][2], blo[4][2];
            #pragma unroll
            for (int ni = 0; ni < 4; ni++) {
                int n = wn*32 + ni*8 + (lane & 7);
                uint32_t soff = SWZ((uint32_t)(n*128 + (kb + ((lane >> 3) & 1)*8)*2));
                ldm_x2(bhi[ni], sbBhi + soff);
                ldm_x2(blo[ni], sbBlo + soff);
            }
            #pragma unroll
            for (int mi = 0; mi < 4; mi++) {
                int m = wm*64 + mi*16 + (lane & 15);
                uint32_t soff = SWZ((uint32_t)(m*128 + (kb + (lane >> 4)*8)*2));
                uint32_t ahi[4], alo[4];
                ldm_x4(ahi, sbAhi + soff);
                ldm_x4(alo, sbAlo + soff);
                #pragma unroll
                for (int ni = 0; ni < 4; ni++) {
                    mma16816(acc[mi][ni], ahi, bhi[ni]);
                    mma16816(acc[mi][ni], ahi, blo[ni]);
                    mma16816(acc[mi][ni], alo, bhi[ni]);
                }
            }
        }
    }

    if (!POOL) {
        // epilogue: bias + relu + split-store h as bf16 hi/lo
        #pragma unroll
        for (int mi = 0; mi < 4; mi++) {
            int r0 = row0 + wm*64 + mi*16 + (lane >> 2);
            #pragma unroll
            for (int ni = 0; ni < 4; ni++) {
                int col = wn*32 + ni*8 + (lane & 3)*2;
                float b0 = __ldg(&bias[col]), b1 = __ldg(&bias[col + 1]);
                float o0x = acc[mi][ni][0] + b0, o0y = acc[mi][ni][1] + b1;
                float o1x = acc[mi][ni][2] + b0, o1y = acc[mi][ni][3] + b1;
                o0x = o0x > 0.f ? o0x : 0.f; o0y = o0y > 0.f ? o0y : 0.f;
                o1x = o1x > 0.f ? o1x : 0.f; o1y = o1y > 0.f ? o1y : 0.f;
                uint32_t h0, l0, h1, l1;
                bsplit2(o0x, o0y, h0, l0);
                bsplit2(o1x, o1y, h1, l1);
                size_t oa = (size_t)r0*DD + col, ob = (size_t)(r0 + 8)*DD + col;
                *(uint32_t*)(CH + oa) = h0; *(uint32_t*)(CL + oa) = l0;
                *(uint32_t*)(CH + ob) = h1; *(uint32_t*)(CL + ob) = l1;
            }
        }
    } else {
        // epilogue: bias + relu + per-graph max pool (CTA == graph)
        __syncthreads();
        int* red = (int*)smem;                   // 128 ints
        if (tid < 128) red[tid] = 0;             // relu >= 0 -> 0-bits identity
        __syncthreads();
        #pragma unroll
        for (int ni = 0; ni < 4; ni++) {
            int col = wn*32 + ni*8 + (lane & 3)*2;
            float b0 = __ldg(&bias[col]), b1 = __ldg(&bias[col + 1]);
            float m0 = 0.f, m1 = 0.f;
            #pragma unroll
            for (int mi = 0; mi < 4; mi++) {
                m0 = fmaxf(m0, fmaxf(acc[mi][ni][0] + b0, acc[mi][ni][2] + b0));
                m1 = fmaxf(m1, fmaxf(acc[mi][ni][1] + b1, acc[mi][ni][3] + b1));
            }
            m0 = m0 > 0.f ? m0 : 0.f;
            m1 = m1 > 0.f ? m1 : 0.f;
            atomicMax(&red[col],     __float_as_int(m0));
            atomicMax(&red[col + 1], __float_as_int(m1));
        }
        __syncthreads();
        if (tid < 128)
            Cpool[(size_t)blockIdx.x*DD + tid] = __int_as_float(red[tid]);
    }
}

extern "C" void kernel_launch(void* const* d_in, const int* in_sizes, int n_in,
                              void* d_out, int out_size) {
    const float* x      = (const float*)d_in[0];
    const int*   ei     = (const int*)  d_in[1];
    const int*   ea     = (const int*)  d_in[2];
    const float* W_emb  = (const float*)d_in[3];
    const float* b_emb  = (const float*)d_in[4];
    const float* W_root = (const float*)d_in[5];
    const float* W_rel  = (const float*)d_in[6];
    const float* bias   = (const float*)d_in[7];
    float* out = (float*)d_out;

    __nv_bfloat16 *hH0, *hL0, *hH1, *hL1, *bhi, *blo;
    cudaGetSymbolAddress((void**)&hH0, g_hH);
    cudaGetSymbolAddress((void**)&hL0, g_hL);
    hH1 = hH0 + (size_t)NN*DD;
    hL1 = hL0 + (size_t)NN*DD;
    cudaGetSymbolAddress((void**)&bhi, g_Bhi);
    cudaGetSymbolAddress((void**)&blo, g_Blo);

    cudaFuncSetAttribute(k_gemm_mma<false>, cudaFuncAttributeMaxDynamicSharedMemorySize, GEMM_SMEM);
    cudaFuncSetAttribute(k_gemm_mma<true>,  cudaFuncAttributeMaxDynamicSharedMemorySize, GEMM_SMEM);
    cudaFuncSetAttribute(k_gather_g, cudaFuncAttributeMaxDynamicSharedMemorySize, 65536);

    k_zero_cnt<<<SEGS/256, 256>>>();
    k_count<<<EE/256, 256>>>(ei, ea);
    k_scan1<<<256, 256>>>();
    k_scan2<<<1, 256>>>();
    k_scan3<<<SEGS/256, 256>>>();
    k_fill<<<EE/256, 256>>>(ei, ea);
    k_wsplit<<<(2*KTOT*DD)/256, 256>>>(W_root, W_rel);
    k_embed<<<NN/64, 256>>>(x, W_emb, b_emb, hH0, hL0);

    // layer 0: h0 -> h1
    k_gather_g<<<GG, 512, 65536>>>(hH0, hL0);
    k_gemm_mma<false><<<NN/128, 256, GEMM_SMEM>>>(hH0, hL0, bhi, blo, bias,
                                                  hH1, hL1, nullptr);
    // layer 1: h1 -> pooled out
    k_gather_g<<<GG, 512, 65536>>>(hH1, hL1);
    k_gemm_mma<true><<<NN/128, 256, GEMM_SMEM>>>(hH1, hL1,
            bhi + (size_t)DD*KTOT, blo + (size_t)DD*KTOT, bias + DD,
            nullptr, nullptr, out);
}

// round 15
// speedup vs baseline: 1.4275x; 1.4275x over previous
#include <cuda_runtime.h>
#include <cuda_bf16.h>
#include <cstdint>

#define NN   65536          // total nodes (G*N)
#define FIN  64
#define DD   128
#define RR   4
#define EE   1572864
#define GG   512
#define SEGS (NN*RR)        // 262144 (node,relation) segments
#define KCAT (RR*DD)        // 512
#define KTOT 640            // 128 (root) + 512 (rel)

// ---- scratch (static device globals; no runtime allocation) ----
__device__ __align__(16) float g_hA[(size_t)NN*DD];       // 32 MB
__device__ __align__(16) float g_hB[(size_t)NN*DD];       // 32 MB
__device__ __align__(16) float g_mean[(size_t)SEGS*DD];   // 134 MB
__device__ __align__(16) int   g_cnt[SEGS];
__device__ __align__(16) int   g_off[SEGS];
__device__ int   g_cur[SEGS];
__device__ int   g_bsum[256];
__device__ int   g_csr[EE];
// weights split to bf16 hi/lo, transposed to [layer][n=128][k=640]
__device__ __align__(16) __nv_bfloat16 g_Bhi[2*128*KTOT];
__device__ __align__(16) __nv_bfloat16 g_Blo[2*128*KTOT];

// ---------------- helpers ----------------
__device__ __forceinline__ uint32_t smem_u32(const void* p) {
    uint32_t a;
    asm("{ .reg .u64 t; cvta.to.shared.u64 t, %1; cvt.u32.u64 %0, t; }" : "=r"(a) : "l"(p));
    return a;
}
#define SWZ(o) ((o) ^ (((o) >> 3) & 0x70))

__device__ __forceinline__ void cp16(uint32_t saddr, const void* g) {
    asm volatile("cp.async.cg.shared.global [%0], [%1], 16;" :: "r"(saddr), "l"(g));
}
#define CP_COMMIT() asm volatile("cp.async.commit_group;")
#define CP_WAIT0()  asm volatile("cp.async.wait_group 0;")

__device__ __forceinline__ void ldm_x4(uint32_t* r, uint32_t addr) {
    asm volatile("ldmatrix.sync.aligned.m8n8.x4.shared.b16 {%0,%1,%2,%3}, [%4];"
        : "=r"(r[0]), "=r"(r[1]), "=r"(r[2]), "=r"(r[3]) : "r"(addr));
}
__device__ __forceinline__ void ldm_x2(uint32_t* r, uint32_t addr) {
    asm volatile("ldmatrix.sync.aligned.m8n8.x2.shared.b16 {%0,%1}, [%2];"
        : "=r"(r[0]), "=r"(r[1]) : "r"(addr));
}
__device__ __forceinline__ void mma16816(float* c, const uint32_t* a, const uint32_t* b) {
    asm volatile("mma.sync.aligned.m16n8k16.row.col.f32.bf16.bf16.f32 "
        "{%0,%1,%2,%3}, {%4,%5,%6,%7}, {%8,%9}, {%0,%1,%2,%3};"
        : "+f"(c[0]), "+f"(c[1]), "+f"(c[2]), "+f"(c[3])
        : "r"(a[0]), "r"(a[1]), "r"(a[2]), "r"(a[3]), "r"(b[0]), "r"(b[1]));
}

// ---------------- CSR build ----------------
__global__ void k_zero_cnt() {
    int i = blockIdx.x*blockDim.x + threadIdx.x;
    if (i < SEGS) g_cnt[i] = 0;
}
__global__ void k_count(const int* __restrict__ ei, const int* __restrict__ ea) {
    int e = blockIdx.x*blockDim.x + threadIdx.x;
    if (e < EE) atomicAdd(&g_cnt[ei[EE + e]*RR + ea[e]], 1);
}
__global__ void k_scan1() {
    __shared__ int s[256];
    int tid = threadIdx.x;
    int base = blockIdx.x*1024 + tid*4;
    int4 c = *(const int4*)&g_cnt[base];
    int sum = c.x + c.y + c.z + c.w;
    s[tid] = sum;
    __syncthreads();
    #pragma unroll
    for (int off = 1; off < 256; off <<= 1) {
        int v = (tid >= off) ? s[tid - off] : 0;
        __syncthreads(); s[tid] += v; __syncthreads();
    }
    int excl = s[tid] - sum;
    int4 o; o.x = excl; o.y = o.x + c.x; o.z = o.y + c.y; o.w = o.z + c.z;
    *(int4*)&g_off[base] = o;
    if (tid == 255) g_bsum[blockIdx.x] = s[255];
}
__global__ void k_scan2() {
    __shared__ int s[256];
    int tid = threadIdx.x;
    int v0 = g_bsum[tid];
    s[tid] = v0;
    __syncthreads();
    #pragma unroll
    for (int off = 1; off < 256; off <<= 1) {
        int v = (tid >= off) ? s[tid - off] : 0;
        __syncthreads(); s[tid] += v; __syncthreads();
    }
    g_bsum[tid] = s[tid] - v0;
}
__global__ void k_scan3() {
    int i = blockIdx.x*blockDim.x + threadIdx.x;
    int o = g_off[i] + g_bsum[i >> 10];
    g_off[i] = o; g_cur[i] = o;
}
__global__ void k_fill(const int* __restrict__ ei, const int* __restrict__ ea) {
    int e = blockIdx.x*blockDim.x + threadIdx.x;
    if (e >= EE) return;
    int seg = ei[EE + e]*RR + ea[e];
    int pos = atomicAdd(&g_cur[seg], 1);
    g_csr[pos] = ei[e];
}

// ---------------- weight split: Wcat[k][n] -> bf16 hi/lo at [l][n][k] -------
__global__ void k_wsplit(const float* __restrict__ W_root, const float* __restrict__ W_rel) {
    int idx = blockIdx.x*blockDim.x + threadIdx.x;     // 2*640*128
    int l = idx / (KTOT*DD);
    int rem = idx - l*(KTOT*DD);
    int k = rem >> 7, n = rem & 127;
    float w = (k < DD) ? W_root[(size_t)l*DD*DD + k*DD + n]
                       : W_rel[(size_t)l*KCAT*DD + (k - DD)*DD + n];
    __nv_bfloat16 hi = __float2bfloat16_rn(w);
    __nv_bfloat16 lo = __float2bfloat16_rn(w - __bfloat162float(hi));
    size_t d = ((size_t)l*DD + n)*KTOT + k;
    g_Bhi[d] = hi; g_Blo[d] = lo;
}

// ---------------- embed: h = x @ W_emb + b_emb (smem-blocked) ----------------
__global__ __launch_bounds__(256) void k_embed(
    const float* __restrict__ x, const float* __restrict__ W,
    const float* __restrict__ b)
{
    __shared__ float xs[64][64];
    __shared__ float ws[64][128];
    int tid = threadIdx.x;
    int row0 = blockIdx.x * 64;
    #pragma unroll
    for (int i = 0; i < 4; i++) {
        int id = i*256 + tid;
        int r = id >> 4, c4 = (id & 15) * 4;
        *(float4*)&xs[r][c4] = *(const float4*)(x + (size_t)(row0 + r)*FIN + c4);
    }
    #pragma unroll
    for (int i = 0; i < 8; i++) {
        int id = i*256 + tid;
        int r = id >> 5, c4 = (id & 31) * 4;
        *(float4*)&ws[r][c4] = *(const float4*)(W + r*DD + c4);
    }
    __syncthreads();
    int ty = tid >> 5, tx = tid & 31;
    float acc[8][4] = {};
    #pragma unroll
    for (int k = 0; k < 64; k++) {
        float4 wv = *(const float4*)&ws[k][tx*4];
        #pragma unroll
        for (int i = 0; i < 8; i++) {
            float xv = xs[ty*8 + i][k];
            acc[i][0] += xv*wv.x; acc[i][1] += xv*wv.y;
            acc[i][2] += xv*wv.z; acc[i][3] += xv*wv.w;
        }
    }
    float4 bv = *(const float4*)(b + tx*4);
    #pragma unroll
    for (int i = 0; i < 8; i++) {
        float4 o;
        o.x = acc[i][0] + bv.x; o.y = acc[i][1] + bv.y;
        o.z = acc[i][2] + bv.z; o.w = acc[i][3] + bv.w;
        *(float4*)(g_hA + (size_t)(row0 + ty*8 + i)*DD + tx*4) = o;
    }
}

// ---------------- gather-mean, per-graph smem version ------------------------
// One CTA per graph loads the graph's 128x128 h tile into smem (cp.async) and
// computes all 512 (node,relation) segment means from smem.
__global__ __launch_bounds__(512) void k_gather_g(const float* __restrict__ h) {
    extern __shared__ float hs[];                 // 128 rows x 128 cols = 64 KB
    int g = blockIdx.x;
    int tid = threadIdx.x;
    uint32_t sb = smem_u32(hs);

    const float4* src = (const float4*)(h + (size_t)g*128*DD);
    #pragma unroll
    for (int i = 0; i < 8; i++)                   // 4096 float4 / 512 threads
        cp16(sb + (i*512 + tid)*16, src + i*512 + tid);
    CP_COMMIT();
    CP_WAIT0();
    __syncthreads();

    int wid = tid >> 5, lane = tid & 31;
    #pragma unroll 1
    for (int s = wid; s < 512; s += 16) {
        int seg = g*512 + s;                      // (node*RR + rel), node local s>>2
        int beg = g_off[seg], n = g_cnt[seg];
        float4 acc = make_float4(0.f, 0.f, 0.f, 0.f);
        const float* hb = hs + lane*4;
        int i = 0;
        for (; i + 2 <= n; i += 2) {
            int s0 = g_csr[beg + i] & 127, s1 = g_csr[beg + i + 1] & 127;
            float4 v0 = *(const float4*)(hb + s0*DD);
            float4 v1 = *(const float4*)(hb + s1*DD);
            acc.x += v0.x + v1.x; acc.y += v0.y + v1.y;
            acc.z += v0.z + v1.z; acc.w += v0.w + v1.w;
        }
        if (i < n) {
            float4 v0 = *(const float4*)(hb + (g_csr[beg + i] & 127)*DD);
            acc.x += v0.x; acc.y += v0.y; acc.z += v0.z; acc.w += v0.w;
        }
        float inv = 1.0f / (float)(n > 0 ? n : 1);
        acc.x *= inv; acc.y *= inv; acc.z *= inv; acc.w *= inv;
        *(float4*)(g_mean + (size_t)seg*DD + lane*4) = acc;
    }
}

// ---------------- tensor-core GEMM via mma.sync --------------------------------
// C[65536,128] = relu([h | g_mean] @ [W_root; W_rel] + bias), bf16x3 HMMA.
// BM=128, BN=128, BK=64, 8 warps 2(m)x4(n), warp tile 64x32.
// smem: Ahi@0 Alo@16K Bhi@32K Blo@48K, SW128-swizzled 128B rows.
// B tiles copied with cp.async (issued before A-convert to overlap).
// POOL=true: CTA == one graph; max-reduce relu outputs into out[g].
#define GEMM_SMEM 65536

template<bool POOL>
__global__ __launch_bounds__(256, 2) void k_gemm_mma(
    const float* __restrict__ A1,
    const __nv_bfloat16* __restrict__ Bhi,
    const __nv_bfloat16* __restrict__ Blo,
    const float* __restrict__ bias,
    float* __restrict__ C)
{
    extern __shared__ char smem[];
    uint32_t sb = smem_u32(smem);
    const uint32_t sbAhi = sb, sbAlo = sb + 16384, sbBhi = sb + 32768, sbBlo = sb + 49152;
    int tid = threadIdx.x, wid = tid >> 5, lane = tid & 31;
    int wm = wid >> 2, wn = wid & 3;            // 2 x 4 warp grid
    int row0 = blockIdx.x * 128;

    float acc[4][4][4];
    #pragma unroll
    for (int i = 0; i < 4; i++)
        #pragma unroll
        for (int j = 0; j < 4; j++)
            #pragma unroll
            for (int q = 0; q < 4; q++) acc[i][j][q] = 0.f;

    for (int kc = 0; kc < 10; kc++) {
        int k0 = kc * 64;
        const float* Asrc; int lda, kA;
        if (k0 < DD) { Asrc = A1; lda = DD; kA = k0; }
        else         { Asrc = g_mean; lda = KCAT; kA = k0 - DD; }

        __syncthreads();   // previous iteration's consumers done with smem

        // B: 128 n-rows x 64 k-cols bf16 via cp.async (16B each), issued first
        #pragma unroll
        for (int i = 0; i < 4; i++) {
            int id = i*256 + tid;                 // 0..1023
            int n = id >> 3, c8 = (id & 7) * 8;   // 8 bf16 = 16B
            size_t gsrc = (size_t)n*KTOT + k0 + c8;
            uint32_t so = SWZ((uint32_t)(n*128 + c8*2));
            cp16(sbBhi + so, Bhi + gsrc);
            cp16(sbBlo + so, Blo + gsrc);
        }
        CP_COMMIT();

        // A: 128 rows x 64 fp32 -> bf16 hi/lo, SW128-swizzled 128B rows
        #pragma unroll
        for (int i = 0; i < 8; i++) {
            int id = i*256 + tid;                 // 0..2047
            int r = id >> 4, c4 = (id & 15) * 4;
            float4 v = __ldcs((const float4*)(Asrc + (size_t)(row0 + r)*lda + kA + c4));
            __nv_bfloat162 h01 = __floats2bfloat162_rn(v.x, v.y);
            __nv_bfloat162 h23 = __floats2bfloat162_rn(v.z, v.w);
            float lx = v.x - __bfloat162float(__low2bfloat16(h01));
            float ly = v.y - __bfloat162float(__high2bfloat16(h01));
            float lz = v.z - __bfloat162float(__low2bfloat16(h23));
            float lw = v.w - __bfloat162float(__high2bfloat16(h23));
            __nv_bfloat162 l01 = __floats2bfloat162_rn(lx, ly);
            __nv_bfloat162 l23 = __floats2bfloat162_rn(lz, lw);
            uint32_t off = SWZ((uint32_t)(r*128 + c4*2));
            uint2 hp, lp;
            hp.x = *(uint32_t*)&h01; hp.y = *(uint32_t*)&h23;
            lp.x = *(uint32_t*)&l01; lp.y = *(uint32_t*)&l23;
            *(uint2*)(smem + off)         = hp;
            *(uint2*)(smem + 16384 + off) = lp;
        }
        CP_WAIT0();
        __syncthreads();

        #pragma unroll
        for (int ks = 0; ks < 4; ks++) {
            int kb = ks * 16;
            uint32_t bhi[4][2], blo[4][2];
            #pragma unroll
            for (int ni = 0; ni < 4; ni++) {
                int n = wn*32 + ni*8 + (lane & 7);
                uint32_t off = SWZ((uint32_t)(n*128 + (kb + ((lane >> 3) & 1)*8)*2));
                ldm_x2(bhi[ni], sbBhi + off);
                ldm_x2(blo[ni], sbBlo + off);
            }
            #pragma unroll
            for (int mi = 0; mi < 4; mi++) {
                int m = wm*64 + mi*16 + (lane & 15);
                uint32_t off = SWZ((uint32_t)(m*128 + (kb + (lane >> 4)*8)*2));
                uint32_t ahi[4], alo[4];
                ldm_x4(ahi, sbAhi + off);
                ldm_x4(alo, sbAlo + off);
                #pragma unroll
                for (int ni = 0; ni < 4; ni++) {
                    mma16816(acc[mi][ni], ahi, bhi[ni]);
                    mma16816(acc[mi][ni], ahi, blo[ni]);
                    mma16816(acc[mi][ni], alo, bhi[ni]);
                }
            }
        }
    }

    if (!POOL) {
        #pragma unroll
        for (int mi = 0; mi < 4; mi++) {
            int r0 = row0 + wm*64 + mi*16 + (lane >> 2);
            #pragma unroll
            for (int ni = 0; ni < 4; ni++) {
                int col = wn*32 + ni*8 + (lane & 3)*2;
                float b0 = __ldg(&bias[col]), b1 = __ldg(&bias[col + 1]);
                float2 o0, o1;
                o0.x = acc[mi][ni][0] + b0; o0.y = acc[mi][ni][1] + b1;
                o1.x = acc[mi][ni][2] + b0; o1.y = acc[mi][ni][3] + b1;
                o0.x = o0.x > 0.f ? o0.x : 0.f; o0.y = o0.y > 0.f ? o0.y : 0.f;
                o1.x = o1.x > 0.f ? o1.x : 0.f; o1.y = o1.y > 0.f ? o1.y : 0.f;
                *(float2*)(C + (size_t)r0*DD + col)       = o0;
                *(float2*)(C + (size_t)(r0 + 8)*DD + col) = o1;
            }
        }
    } else {
        __syncthreads();
        int* red = (int*)smem;                   // 128 ints
        if (tid < 128) red[tid] = 0;             // relu >= 0 -> 0-bits identity
        __syncthreads();
        #pragma unroll
        for (int ni = 0; ni < 4; ni++) {
            int col = wn*32 + ni*8 + (lane & 3)*2;
            float b0 = __ldg(&bias[col]), b1 = __ldg(&bias[col + 1]);
            float m0 = 0.f, m1 = 0.f;
            #pragma unroll
            for (int mi = 0; mi < 4; mi++) {
                m0 = fmaxf(m0, fmaxf(acc[mi][ni][0] + b0, acc[mi][ni][2] + b0));
                m1 = fmaxf(m1, fmaxf(acc[mi][ni][1] + b1, acc[mi][ni][3] + b1));
            }
            m0 = m0 > 0.f ? m0 : 0.f;
            m1 = m1 > 0.f ? m1 : 0.f;
            atomicMax(&red[col],     __float_as_int(m0));
            atomicMax(&red[col + 1], __float_as_int(m1));
        }
        __syncthreads();
        if (tid < 128)
            C[(size_t)blockIdx.x*DD + tid] = __int_as_float(red[tid]);
    }
}

extern "C" void kernel_launch(void* const* d_in, const int* in_sizes, int n_in,
                              void* d_out, int out_size) {
    const float* x      = (const float*)d_in[0];
    const int*   ei     = (const int*)  d_in[1];
    const int*   ea     = (const int*)  d_in[2];
    const float* W_emb  = (const float*)d_in[3];
    const float* b_emb  = (const float*)d_in[4];
    const float* W_root = (const float*)d_in[5];
    const float* W_rel  = (const float*)d_in[6];
    const float* bias   = (const float*)d_in[7];
    float* out = (float*)d_out;

    float *hA, *hB;
    cudaGetSymbolAddress((void**)&hA, g_hA);
    cudaGetSymbolAddress((void**)&hB, g_hB);
    __nv_bfloat16 *bhi, *blo;
    cudaGetSymbolAddress((void**)&bhi, g_Bhi);
    cudaGetSymbolAddress((void**)&blo, g_Blo);

    cudaFuncSetAttribute(k_gemm_mma<false>, cudaFuncAttributeMaxDynamicSharedMemorySize, GEMM_SMEM);
    cudaFuncSetAttribute(k_gemm_mma<true>,  cudaFuncAttributeMaxDynamicSharedMemorySize, GEMM_SMEM);
    cudaFuncSetAttribute(k_gather_g, cudaFuncAttributeMaxDynamicSharedMemorySize, 65536);

    k_zero_cnt<<<SEGS/256, 256>>>();
    k_count<<<EE/256, 256>>>(ei, ea);
    k_scan1<<<256, 256>>>();
    k_scan2<<<1, 256>>>();
    k_scan3<<<SEGS/256, 256>>>();
    k_fill<<<EE/256, 256>>>(ei, ea);
    k_wsplit<<<(2*KTOT*DD)/256, 256>>>(W_root, W_rel);
    k_embed<<<NN/64, 256>>>(x, W_emb, b_emb);

    // layer 0: h -> h
    k_gather_g<<<GG, 512, 65536>>>(hA);
    k_gemm_mma<false><<<NN/128, 256, GEMM_SMEM>>>(hA, bhi, blo, bias, hB);
    // layer 1: h -> pooled out (no h store)
    k_gather_g<<<GG, 512, 65536>>>(hB);
    k_gemm_mma<true><<<NN/128, 256, GEMM_SMEM>>>(hB,
            bhi + (size_t)DD*KTOT, blo + (size_t)DD*KTOT, bias + DD, out);
}